// round 4
// baseline (speedup 1.0000x reference)
#include <cuda_runtime.h>

#define NMAX 100000
#define NLYR 3

// Device scratch.
// g_all : [N, 512]  concatenated embeddings (block0 raw emb, blocks 1..3 normalized)
// g_ego : [N, 128]  UNNORMALIZED ego propagated between layers
// g_msg : [N, 128]  segment-sum accumulator (returned to zero each layer)
// g_wPack: [l][k=0..255][od] stacked: k<128 -> gc_w[l][od][k], else bi_w[l][od][k-128]
__device__ __align__(16) float g_all[(size_t)NMAX * 512];
__device__ __align__(16) float g_ego[(size_t)NMAX * 128];
__device__ __align__(16) float g_msg[(size_t)NMAX * 128];
__device__ __align__(16) float g_wPack[NLYR * 256 * 128];

// packed f32x2 fma: d = a*b + d (2 independent fp32 lanes per instruction)
__device__ __forceinline__ void fma2(unsigned long long& d,
                                     unsigned long long a,
                                     unsigned long long b) {
    asm("fma.rn.f32x2 %0, %1, %2, %0;" : "+l"(d) : "l"(a), "l"(b));
}
__device__ __forceinline__ float lo32(unsigned long long x) {
    return __uint_as_float((unsigned)(x & 0xffffffffu));
}
__device__ __forceinline__ float hi32(unsigned long long x) {
    return __uint_as_float((unsigned)(x >> 32));
}

// ---------------------------------------------------------------------------
__global__ void pack_weights(const float* __restrict__ gw,
                             const float* __restrict__ bw) {
    int idx = blockIdx.x * blockDim.x + threadIdx.x;
    if (idx >= NLYR * 256 * 128) return;
    int l  = idx >> 15;
    int r  = idx & 32767;
    int k  = r >> 7;
    int od = r & 127;
    float v = (k < 128) ? gw[l * 16384 + od * 128 + k]
                        : bw[l * 16384 + od * 128 + (k - 128)];
    g_wPack[idx] = v;
}

// ---------------------------------------------------------------------------
__global__ void init_copy(const float4* __restrict__ emb4, int n) {
    int i = blockIdx.x * blockDim.x + threadIdx.x;
    if (i >= n * 32) return;
    int node = i >> 5, d4 = i & 31;
    float4 v = emb4[i];
    ((float4*)g_all)[(size_t)node * 128 + d4] = v;
    ((float4*)g_ego)[i] = v;
    ((float4*)g_msg)[i] = make_float4(0.f, 0.f, 0.f, 0.f);
}

// ---------------------------------------------------------------------------
// SpMM: msg[row] += w * ego[col]. One warp per edge, float4 atomics (RED.128).
// ---------------------------------------------------------------------------
__global__ void spmm(const int* __restrict__ ei, const float* __restrict__ ew,
                     int E) {
    int gt = blockIdx.x * blockDim.x + threadIdx.x;
    int e = gt >> 5, lane = gt & 31;
    if (e >= E) return;
    int row = ei[e];
    int col = ei[E + e];
    float w = ew[e];
    float4 v = ((const float4*)g_ego)[(size_t)col * 32 + lane];
    v.x *= w; v.y *= w; v.z *= w; v.w *= w;
    atomicAdd(((float4*)g_msg) + (size_t)row * 32 + lane, v);
}

// ---------------------------------------------------------------------------
// Fused layer GEMM, f32x2, register tile 4 nodes x 8 ods per thread.
//   C[64 nodes][128 od] = A[64][256] * B[256][128]   (A = [msg | ego*msg])
//   ego' = leaky_relu(C + bias, 0.2) -> g_ego ; normalized -> g_all block l+1
//   zeroes g_msg rows afterwards.
// Block 256 thr = 8 warps. lane&15 -> od octet, lane>>4 + warp -> node quad.
// A stored DUPLICATED in smem ((a,a) pairs) -> LDS yields packed multiplicands.
// ---------------------------------------------------------------------------
__global__ __launch_bounds__(256) void fused_layer(
        const float* __restrict__ gcb, const float* __restrict__ bib,
        int n, int layer) {
    __shared__ __align__(16) float As2[32 * 128];   // [kc][2*node] dup, 16KB
    __shared__ __align__(16) float Bs[32 * 128];    // [kc][od], 16KB

    const int tid  = threadIdx.x;
    const int lane = tid & 31;
    const int warp = tid >> 5;
    const int odl  = lane & 15;               // od octet: ods 8*odl .. 8*odl+7
    const int nodeBase = warp * 8 + (lane >> 4) * 4;  // 4 nodes
    const int nb   = blockIdx.x * 64;
    const int loff = layer * 128;
    const float* wP = g_wPack + layer * 32768;

    unsigned long long acc[4][4];
#pragma unroll
    for (int i = 0; i < 4; ++i)
#pragma unroll
        for (int j = 0; j < 4; ++j) acc[i][j] = 0ull;

    for (int c = 0; c < 8; ++c) {               // K chunks of 32
        __syncthreads();
        // --- B chunk: Bs[k][od] = wP[(c*32+k)*128+od], 1024 float4, coalesced
        {
            const float4* src = (const float4*)(wP + c * 32 * 128);
            float4* dst = (float4*)Bs;
#pragma unroll
            for (int i = 0; i < 4; ++i) dst[tid + 256 * i] = src[tid + 256 * i];
        }
        // --- A chunk (duplicated): 512 tasks, each loads one float4 of A
        {
#pragma unroll
            for (int i = 0; i < 2; ++i) {
                int idx  = tid + 256 * i;       // 0..511
                int node = idx & 63;
                int k4   = idx >> 6;            // 0..7
                int g    = nb + node;
                int kk   = c * 32 + k4 * 4;
                float4 m = make_float4(0.f, 0.f, 0.f, 0.f);
                if (g < n) {
                    if (kk < 128) {
                        m = *(const float4*)(g_msg + (size_t)g * 128 + kk);
                    } else {
                        m = *(const float4*)(g_msg + (size_t)g * 128 + kk - 128);
                        float4 e = *(const float4*)(g_ego + (size_t)g * 128 + kk - 128);
                        m.x *= e.x; m.y *= e.y; m.z *= e.z; m.w *= e.w;
                    }
                }
                float* base = As2 + (k4 * 4) * 128 + 2 * node;
                *(float2*)(base)       = make_float2(m.x, m.x);
                *(float2*)(base + 128) = make_float2(m.y, m.y);
                *(float2*)(base + 256) = make_float2(m.z, m.z);
                *(float2*)(base + 384) = make_float2(m.w, m.w);
            }
        }
        __syncthreads();
        // --- compute 32 k-steps: 4 LDS.128 + 16 FFMA2 per k per thread
#pragma unroll 8
        for (int k = 0; k < 32; ++k) {
            const ulonglong2* Bu = (const ulonglong2*)(Bs + k * 128);
            ulonglong2 b0 = Bu[odl * 2];        // ods 8odl..+3
            ulonglong2 b1 = Bu[odl * 2 + 1];    // ods 8odl+4..+7
            const ulonglong2* Au =
                (const ulonglong2*)(As2 + k * 128 + 2 * nodeBase);
            ulonglong2 a01 = Au[0];             // (n0,n0),(n1,n1)
            ulonglong2 a23 = Au[1];             // (n2,n2),(n3,n3)
            fma2(acc[0][0], a01.x, b0.x); fma2(acc[0][1], a01.x, b0.y);
            fma2(acc[0][2], a01.x, b1.x); fma2(acc[0][3], a01.x, b1.y);
            fma2(acc[1][0], a01.y, b0.x); fma2(acc[1][1], a01.y, b0.y);
            fma2(acc[1][2], a01.y, b1.x); fma2(acc[1][3], a01.y, b1.y);
            fma2(acc[2][0], a23.x, b0.x); fma2(acc[2][1], a23.x, b0.y);
            fma2(acc[2][2], a23.x, b1.x); fma2(acc[2][3], a23.x, b1.y);
            fma2(acc[3][0], a23.y, b0.x); fma2(acc[3][1], a23.y, b0.y);
            fma2(acc[3][2], a23.y, b1.x); fma2(acc[3][3], a23.y, b1.y);
        }
    }

    // --- epilogue: bias, leaky_relu, L2 norm over 16 od-lanes, stores ---
    float bias[8];
    {
        float4 bg0 = *(const float4*)(gcb + loff + 8 * odl);
        float4 bg1 = *(const float4*)(gcb + loff + 8 * odl + 4);
        float4 bb0 = *(const float4*)(bib + loff + 8 * odl);
        float4 bb1 = *(const float4*)(bib + loff + 8 * odl + 4);
        bias[0] = bg0.x + bb0.x; bias[1] = bg0.y + bb0.y;
        bias[2] = bg0.z + bb0.z; bias[3] = bg0.w + bb0.w;
        bias[4] = bg1.x + bb1.x; bias[5] = bg1.y + bb1.y;
        bias[6] = bg1.z + bb1.z; bias[7] = bg1.w + bb1.w;
    }

    float v[4][8];
    float s[4];
#pragma unroll
    for (int nn = 0; nn < 4; ++nn) {
        float sum = 0.f;
#pragma unroll
        for (int j = 0; j < 4; ++j) {
            float x0 = lo32(acc[nn][j]) + bias[2 * j];
            float x1 = hi32(acc[nn][j]) + bias[2 * j + 1];
            x0 = (x0 > 0.f) ? x0 : 0.2f * x0;
            x1 = (x1 > 0.f) ? x1 : 0.2f * x1;
            v[nn][2 * j]     = x0;
            v[nn][2 * j + 1] = x1;
            sum += x0 * x0 + x1 * x1;
        }
        s[nn] = sum;
    }
    // reduce across the 16 od-lanes (offsets stay inside each half-warp)
#pragma unroll
    for (int off = 1; off < 16; off <<= 1) {
        s[0] += __shfl_xor_sync(0xffffffffu, s[0], off);
        s[1] += __shfl_xor_sync(0xffffffffu, s[1], off);
        s[2] += __shfl_xor_sync(0xffffffffu, s[2], off);
        s[3] += __shfl_xor_sync(0xffffffffu, s[3], off);
    }
    const float4 z4 = make_float4(0.f, 0.f, 0.f, 0.f);
#pragma unroll
    for (int nn = 0; nn < 4; ++nn) {
        int g = nb + nodeBase + nn;
        if (g < n) {
            float inv = 1.0f / fmaxf(sqrtf(s[nn]), 1e-12f);
            float4 w0 = make_float4(v[nn][0], v[nn][1], v[nn][2], v[nn][3]);
            float4 w1 = make_float4(v[nn][4], v[nn][5], v[nn][6], v[nn][7]);
            *(float4*)(g_ego + (size_t)g * 128 + 8 * odl)     = w0;
            *(float4*)(g_ego + (size_t)g * 128 + 8 * odl + 4) = w1;
            *(float4*)(g_all + (size_t)g * 512 + loff + 128 + 8 * odl) =
                make_float4(w0.x * inv, w0.y * inv, w0.z * inv, w0.w * inv);
            *(float4*)(g_all + (size_t)g * 512 + loff + 128 + 8 * odl + 4) =
                make_float4(w1.x * inv, w1.y * inv, w1.z * inv, w1.w * inv);
            *(float4*)(g_msg + (size_t)g * 128 + 8 * odl)     = z4;
            *(float4*)(g_msg + (size_t)g * 128 + 8 * odl + 4) = z4;
        }
    }
}

// ---------------------------------------------------------------------------
// Scoring: out[q] = dot(all[src[q]], all[dst[q]]) over 512 dims. Warp/query.
// ---------------------------------------------------------------------------
__global__ void score(const int* __restrict__ eli, int Q,
                      float* __restrict__ out) {
    int gt = blockIdx.x * blockDim.x + threadIdx.x;
    int q = gt >> 5, lane = gt & 31;
    if (q >= Q) return;
    int s = eli[q];
    int d = eli[Q + q];
    const float4* a = (const float4*)(g_all + (size_t)s * 512);
    const float4* b = (const float4*)(g_all + (size_t)d * 512);
    float acc = 0.f;
#pragma unroll
    for (int j = 0; j < 4; ++j) {
        float4 x = a[lane + 32 * j];
        float4 y = b[lane + 32 * j];
        acc += x.x * y.x + x.y * y.y + x.z * y.z + x.w * y.w;
    }
#pragma unroll
    for (int off = 16; off; off >>= 1)
        acc += __shfl_xor_sync(0xffffffffu, acc, off);
    if (lane == 0) out[q] = acc;
}

// ---------------------------------------------------------------------------
extern "C" void kernel_launch(void* const* d_in, const int* in_sizes, int n_in,
                              void* d_out, int out_size) {
    const int*   ei  = (const int*)d_in[0];    // edge_index        [2, E]
    const int*   eli = (const int*)d_in[1];    // edge_label_index  [2, Q]
    const float* ew  = (const float*)d_in[2];  // edge_weight       [E]
    const float* emb = (const float*)d_in[3];  // emb               [N, 128]
    const float* gcw = (const float*)d_in[4];  // gc_w              [3,128,128]
    const float* gcb = (const float*)d_in[5];  // gc_b              [3,128]
    const float* biw = (const float*)d_in[6];  // bi_w              [3,128,128]
    const float* bib = (const float*)d_in[7];  // bi_b              [3,128]

    int E = in_sizes[0] / 2;
    int Q = in_sizes[1] / 2;
    int n = in_sizes[3] / 128;
    float* out = (float*)d_out;

    pack_weights<<<(NLYR * 256 * 128 + 255) / 256, 256>>>(gcw, biw);
    init_copy<<<(n * 32 + 255) / 256, 256>>>((const float4*)emb, n);

    for (int l = 0; l < NLYR; ++l) {
        spmm<<<(int)(((size_t)E * 32 + 255) / 256), 256>>>(ei, ew, E);
        fused_layer<<<(n + 63) / 64, 256>>>(gcb, bib, n, l);
    }

    score<<<(int)(((size_t)Q * 32 + 255) / 256), 256>>>(eli, Q, out);
}

// round 5
// speedup vs baseline: 1.3868x; 1.3868x over previous
#include <cuda_runtime.h>

#define NMAX 100000
#define EMAX 1600000
#define NLYR 3

// Device scratch.
__device__ __align__(16) float g_all[(size_t)NMAX * 512];
__device__ __align__(16) float g_ego[(size_t)NMAX * 128];
__device__ __align__(16) float g_msg[(size_t)NMAX * 128];
__device__ __align__(16) float g_wPack[NLYR * 256 * 128];
// CSR built once per launch, reused by all 3 layers.
__device__ int   g_rowptr[NMAX + 1];
__device__ int   g_cnt[NMAX];
__device__ int   g_off[NMAX];
__device__ int   g_ecol[EMAX];
__device__ float g_ewc[EMAX];

// packed f32x2 fma: d = a*b + d
__device__ __forceinline__ void fma2(unsigned long long& d,
                                     unsigned long long a,
                                     unsigned long long b) {
    asm("fma.rn.f32x2 %0, %1, %2, %0;" : "+l"(d) : "l"(a), "l"(b));
}
__device__ __forceinline__ float lo32(unsigned long long x) {
    return __uint_as_float((unsigned)(x & 0xffffffffu));
}
__device__ __forceinline__ float hi32(unsigned long long x) {
    return __uint_as_float((unsigned)(x >> 32));
}

// ---------------------------------------------------------------------------
__global__ void pack_weights(const float* __restrict__ gw,
                             const float* __restrict__ bw) {
    int idx = blockIdx.x * blockDim.x + threadIdx.x;
    if (idx >= NLYR * 256 * 128) return;
    int l  = idx >> 15;
    int r  = idx & 32767;
    int k  = r >> 7;
    int od = r & 127;
    float v = (k < 128) ? gw[l * 16384 + od * 128 + k]
                        : bw[l * 16384 + od * 128 + (k - 128)];
    g_wPack[idx] = v;
}

// ---------------------------------------------------------------------------
// Copy emb into g_all block 0 and g_ego; zero CSR counters.
// ---------------------------------------------------------------------------
__global__ void init_copy(const float4* __restrict__ emb4, int n) {
    int i = blockIdx.x * blockDim.x + threadIdx.x;
    if (i >= n * 32) return;
    int node = i >> 5, d4 = i & 31;
    float4 v = emb4[i];
    ((float4*)g_all)[(size_t)node * 128 + d4] = v;
    ((float4*)g_ego)[i] = v;
    if (d4 == 0) { g_cnt[node] = 0; g_off[node] = 0; }
}

// ---------------------------------------------------------------------------
// CSR build: histogram -> single-block scan -> scatter.
// ---------------------------------------------------------------------------
__global__ void csr_hist(const int* __restrict__ ei, int E) {
    int e = blockIdx.x * blockDim.x + threadIdx.x;
    if (e < E) atomicAdd(&g_cnt[ei[e]], 1);
}

__global__ __launch_bounds__(1024) void csr_scan(int n) {
    __shared__ int part[1024];
    int t = threadIdx.x;
    int chunk = (n + 1023) >> 10;
    int lo = t * chunk;
    int hi = min(lo + chunk, n);
    int s = 0;
    for (int i = lo; i < hi; ++i) s += g_cnt[i];
    part[t] = s;
    __syncthreads();
    for (int off = 1; off < 1024; off <<= 1) {
        int v = (t >= off) ? part[t - off] : 0;
        __syncthreads();
        part[t] += v;
        __syncthreads();
    }
    int base = (t > 0) ? part[t - 1] : 0;
    for (int i = lo; i < hi; ++i) {
        int c = g_cnt[i];
        g_rowptr[i] = base;
        base += c;
    }
    if (t == 1023) g_rowptr[n] = part[1023];
}

__global__ void csr_scatter(const int* __restrict__ ei,
                            const float* __restrict__ ew, int E) {
    int e = blockIdx.x * blockDim.x + threadIdx.x;
    if (e >= E) return;
    int row = ei[e];
    int col = ei[E + e];
    int pos = g_rowptr[row] + atomicAdd(&g_off[row], 1);
    g_ecol[pos] = col;
    g_ewc[pos]  = ew[e];
}

// ---------------------------------------------------------------------------
// SpMM via CSR: msg[row] = sum_e w_e * ego[col_e]. One warp per row,
// register accumulation, single store, ZERO atomics.
// ---------------------------------------------------------------------------
__global__ void spmm_csr(int n) {
    int gt = blockIdx.x * blockDim.x + threadIdx.x;
    int row = gt >> 5, lane = gt & 31;
    if (row >= n) return;
    int beg = g_rowptr[row];
    int end = g_rowptr[row + 1];
    float4 acc = make_float4(0.f, 0.f, 0.f, 0.f);
    for (int b = beg; b < end; b += 32) {
        int idx = b + lane;
        int c = 0; float w = 0.f;
        if (idx < end) { c = g_ecol[idx]; w = g_ewc[idx]; }
        int m = min(32, end - b);
        for (int j = 0; j < m; ++j) {
            int   cc = __shfl_sync(0xffffffffu, c, j);
            float ww = __shfl_sync(0xffffffffu, w, j);
            float4 v = ((const float4*)g_ego)[(size_t)cc * 32 + lane];
            acc.x += ww * v.x; acc.y += ww * v.y;
            acc.z += ww * v.z; acc.w += ww * v.w;
        }
    }
    ((float4*)g_msg)[(size_t)row * 32 + lane] = acc;
}

// ---------------------------------------------------------------------------
// Fused layer GEMM (R3 config: 32 nodes x 128 od, 4n x 4o per thread, f32x2).
// ---------------------------------------------------------------------------
__global__ __launch_bounds__(256) void fused_layer(
        const float* __restrict__ gcb, const float* __restrict__ bib,
        int n, int layer) {
    __shared__ __align__(16) float As2[64 * 64];    // [kc][2*node]  16KB
    __shared__ __align__(16) float Bs[64 * 128];    // [kc][od]      32KB

    const int tid  = threadIdx.x;
    const int tn   = tid >> 5;      // warp id -> node group
    const int to   = tid & 31;      // lane    -> od group
    const int nb   = blockIdx.x * 32;
    const int loff = layer * 128;
    const float* wP = g_wPack + layer * 32768;

    unsigned long long acc[4][2];
#pragma unroll
    for (int i = 0; i < 4; ++i) { acc[i][0] = 0ull; acc[i][1] = 0ull; }

    for (int c = 0; c < 4; ++c) {
        __syncthreads();
        {
            const float4* src = (const float4*)(wP + c * 64 * 128);
            float4* dst = (float4*)Bs;
#pragma unroll
            for (int i = 0; i < 8; ++i) dst[tid + 256 * i] = src[tid + 256 * i];
        }
        {
#pragma unroll
            for (int i = 0; i < 2; ++i) {
                int idx  = tid + 256 * i;      // 0..511
                int node = idx & 31;
                int k4   = idx >> 5;           // 0..15
                int g    = nb + node;
                float4 m = make_float4(0.f, 0.f, 0.f, 0.f);
                int kk = c * 64 + k4 * 4;
                if (g < n) {
                    if (kk < 128) {
                        m = *(const float4*)(g_msg + (size_t)g * 128 + kk);
                    } else {
                        m = *(const float4*)(g_msg + (size_t)g * 128 + kk - 128);
                        float4 e = *(const float4*)(g_ego + (size_t)g * 128 + kk - 128);
                        m.x *= e.x; m.y *= e.y; m.z *= e.z; m.w *= e.w;
                    }
                }
                float* base = As2 + (k4 * 4) * 64 + 2 * node;
                *(float2*)(base)       = make_float2(m.x, m.x);
                *(float2*)(base + 64)  = make_float2(m.y, m.y);
                *(float2*)(base + 128) = make_float2(m.z, m.z);
                *(float2*)(base + 192) = make_float2(m.w, m.w);
            }
        }
        __syncthreads();
        const ulonglong2* Bu = (const ulonglong2*)Bs;
        const ulonglong2* Au = (const ulonglong2*)As2;
#pragma unroll 8
        for (int k = 0; k < 64; ++k) {
            ulonglong2 b   = Bu[k * 32 + to];
            ulonglong2 a01 = Au[k * 16 + 2 * tn];
            ulonglong2 a23 = Au[k * 16 + 2 * tn + 1];
            fma2(acc[0][0], a01.x, b.x); fma2(acc[0][1], a01.x, b.y);
            fma2(acc[1][0], a01.y, b.x); fma2(acc[1][1], a01.y, b.y);
            fma2(acc[2][0], a23.x, b.x); fma2(acc[2][1], a23.x, b.y);
            fma2(acc[3][0], a23.y, b.x); fma2(acc[3][1], a23.y, b.y);
        }
    }

    float4 bias;
    {
        float4 bg = *(const float4*)(gcb + loff + 4 * to);
        float4 bb = *(const float4*)(bib + loff + 4 * to);
        bias = make_float4(bg.x + bb.x, bg.y + bb.y, bg.z + bb.z, bg.w + bb.w);
    }

    float4 v[4];
    float  s[4];
#pragma unroll
    for (int nn = 0; nn < 4; ++nn) {
        float x0 = lo32(acc[nn][0]) + bias.x;
        float x1 = hi32(acc[nn][0]) + bias.y;
        float x2 = lo32(acc[nn][1]) + bias.z;
        float x3 = hi32(acc[nn][1]) + bias.w;
        x0 = (x0 > 0.f) ? x0 : 0.2f * x0;
        x1 = (x1 > 0.f) ? x1 : 0.2f * x1;
        x2 = (x2 > 0.f) ? x2 : 0.2f * x2;
        x3 = (x3 > 0.f) ? x3 : 0.2f * x3;
        v[nn] = make_float4(x0, x1, x2, x3);
        s[nn] = x0 * x0 + x1 * x1 + x2 * x2 + x3 * x3;
    }
#pragma unroll
    for (int off = 16; off; off >>= 1) {
        s[0] += __shfl_xor_sync(0xffffffffu, s[0], off);
        s[1] += __shfl_xor_sync(0xffffffffu, s[1], off);
        s[2] += __shfl_xor_sync(0xffffffffu, s[2], off);
        s[3] += __shfl_xor_sync(0xffffffffu, s[3], off);
    }
#pragma unroll
    for (int nn = 0; nn < 4; ++nn) {
        int g = nb + 4 * tn + nn;
        if (g < n) {
            float inv = 1.0f / fmaxf(sqrtf(s[nn]), 1e-12f);
            float4 w = v[nn];
            *(float4*)(g_ego + (size_t)g * 128 + 4 * to) = w;
            *(float4*)(g_all + (size_t)g * 512 + loff + 128 + 4 * to) =
                make_float4(w.x * inv, w.y * inv, w.z * inv, w.w * inv);
        }
    }
}

// ---------------------------------------------------------------------------
// Scoring: out[q] = dot(all[src[q]], all[dst[q]]) over 512 dims. Warp/query.
// ---------------------------------------------------------------------------
__global__ void score(const int* __restrict__ eli, int Q,
                      float* __restrict__ out) {
    int gt = blockIdx.x * blockDim.x + threadIdx.x;
    int q = gt >> 5, lane = gt & 31;
    if (q >= Q) return;
    int s = eli[q];
    int d = eli[Q + q];
    const float4* a = (const float4*)(g_all + (size_t)s * 512);
    const float4* b = (const float4*)(g_all + (size_t)d * 512);
    float acc = 0.f;
#pragma unroll
    for (int j = 0; j < 4; ++j) {
        float4 x = a[lane + 32 * j];
        float4 y = b[lane + 32 * j];
        acc += x.x * y.x + x.y * y.y + x.z * y.z + x.w * y.w;
    }
#pragma unroll
    for (int off = 16; off; off >>= 1)
        acc += __shfl_xor_sync(0xffffffffu, acc, off);
    if (lane == 0) out[q] = acc;
}

// ---------------------------------------------------------------------------
extern "C" void kernel_launch(void* const* d_in, const int* in_sizes, int n_in,
                              void* d_out, int out_size) {
    const int*   ei  = (const int*)d_in[0];    // edge_index        [2, E]
    const int*   eli = (const int*)d_in[1];    // edge_label_index  [2, Q]
    const float* ew  = (const float*)d_in[2];  // edge_weight       [E]
    const float* emb = (const float*)d_in[3];  // emb               [N, 128]
    const float* gcw = (const float*)d_in[4];  // gc_w              [3,128,128]
    const float* gcb = (const float*)d_in[5];  // gc_b              [3,128]
    const float* biw = (const float*)d_in[6];  // bi_w              [3,128,128]
    const float* bib = (const float*)d_in[7];  // bi_b              [3,128]

    int E = in_sizes[0] / 2;
    int Q = in_sizes[1] / 2;
    int n = in_sizes[3] / 128;
    float* out = (float*)d_out;

    pack_weights<<<(NLYR * 256 * 128 + 255) / 256, 256>>>(gcw, biw);
    init_copy<<<(n * 32 + 255) / 256, 256>>>((const float4*)emb, n);

    // Build CSR once; reused by all 3 layers.
    csr_hist<<<(E + 255) / 256, 256>>>(ei, E);
    csr_scan<<<1, 1024>>>(n);
    csr_scatter<<<(E + 255) / 256, 256>>>(ei, ew, E);

    for (int l = 0; l < NLYR; ++l) {
        spmm_csr<<<(int)(((size_t)n * 32 + 255) / 256), 256>>>(n);
        fused_layer<<<(n + 31) / 32, 256>>>(gcb, bib, n, l);
    }

    score<<<(int)(((size_t)Q * 32 + 255) / 256), 256>>>(eli, Q, out);
}

// round 6
// speedup vs baseline: 1.4855x; 1.0712x over previous
#include <cuda_runtime.h>

#define NMAX 100000
#define EMAX 1600000
#define NLYR 3

// Device scratch.
__device__ __align__(16) float g_all[(size_t)NMAX * 512];
__device__ __align__(16) float g_ego[(size_t)NMAX * 128];
__device__ __align__(16) float g_msg[(size_t)NMAX * 128];
__device__ __align__(16) float g_wPack[NLYR * 256 * 128];
// CSR built once per launch, reused by all 3 layers.
__device__ int   g_rowptr[NMAX];
__device__ int   g_cnt[NMAX];
__device__ int   g_off[NMAX];
__device__ int   g_total;
__device__ int   g_ecol[EMAX];
__device__ float g_ewc[EMAX];

// packed f32x2 fma: d = a*b + d
__device__ __forceinline__ void fma2(unsigned long long& d,
                                     unsigned long long a,
                                     unsigned long long b) {
    asm("fma.rn.f32x2 %0, %1, %2, %0;" : "+l"(d) : "l"(a), "l"(b));
}
__device__ __forceinline__ float lo32(unsigned long long x) {
    return __uint_as_float((unsigned)(x & 0xffffffffu));
}
__device__ __forceinline__ float hi32(unsigned long long x) {
    return __uint_as_float((unsigned)(x >> 32));
}

// ---------------------------------------------------------------------------
__global__ void pack_weights(const float* __restrict__ gw,
                             const float* __restrict__ bw) {
    int idx = blockIdx.x * blockDim.x + threadIdx.x;
    if (idx >= NLYR * 256 * 128) return;
    int l  = idx >> 15;
    int r  = idx & 32767;
    int k  = r >> 7;
    int od = r & 127;
    float v = (k < 128) ? gw[l * 16384 + od * 128 + k]
                        : bw[l * 16384 + od * 128 + (k - 128)];
    g_wPack[idx] = v;
}

// ---------------------------------------------------------------------------
// Copy emb into g_all block 0 and g_ego; zero CSR counters + global cursor.
// ---------------------------------------------------------------------------
__global__ void init_copy(const float4* __restrict__ emb4, int n) {
    int i = blockIdx.x * blockDim.x + threadIdx.x;
    if (i >= n * 32) return;
    int node = i >> 5, d4 = i & 31;
    float4 v = emb4[i];
    ((float4*)g_all)[(size_t)node * 128 + d4] = v;
    ((float4*)g_ego)[i] = v;
    if (d4 == 0) { g_cnt[node] = 0; g_off[node] = 0; }
    if (i == 0) g_total = 0;
}

// ---------------------------------------------------------------------------
// CSR build: histogram -> hierarchical offset reservation -> scatter.
// Row segments are contiguous; their global order is irrelevant to the sum.
// ---------------------------------------------------------------------------
__global__ void csr_hist(const int* __restrict__ ei, int E) {
    int e = blockIdx.x * blockDim.x + threadIdx.x;
    if (e < E) atomicAdd(&g_cnt[ei[e]], 1);
}

__global__ __launch_bounds__(256) void csr_offsets(int n) {
    __shared__ int wbase[8];
    int tid  = threadIdx.x;
    int lane = tid & 31;
    int w    = tid >> 5;
    int i    = blockIdx.x * 256 + tid;
    int cnt  = (i < n) ? g_cnt[i] : 0;

    // inclusive warp scan of cnt
    int pre = cnt;
#pragma unroll
    for (int off = 1; off < 32; off <<= 1) {
        int v = __shfl_up_sync(0xffffffffu, pre, off);
        if (lane >= off) pre += v;
    }
    if (lane == 31) wbase[w] = pre;   // warp total
    __syncthreads();

    if (w == 0) {
        int orig = (lane < 8) ? wbase[lane] : 0;
        int s = orig;
#pragma unroll
        for (int off = 1; off < 8; off <<= 1) {
            int v = __shfl_up_sync(0xffffffffu, s, off);
            if (lane >= off) s += v;
        }
        int total = __shfl_sync(0xffffffffu, s, 7);
        int base = 0;
        if (lane == 7) base = atomicAdd(&g_total, total);
        base = __shfl_sync(0xffffffffu, base, 7);
        if (lane < 8) wbase[lane] = base + s - orig;  // exclusive warp base
    }
    __syncthreads();

    if (i < n) g_rowptr[i] = wbase[w] + pre - cnt;
}

__global__ void csr_scatter(const int* __restrict__ ei,
                            const float* __restrict__ ew, int E) {
    int e = blockIdx.x * blockDim.x + threadIdx.x;
    if (e >= E) return;
    int row = ei[e];
    int col = ei[E + e];
    int pos = g_rowptr[row] + atomicAdd(&g_off[row], 1);
    g_ecol[pos] = col;
    g_ewc[pos]  = ew[e];
}

// ---------------------------------------------------------------------------
// SpMM via CSR: msg[row] = sum_e w_e * ego[col_e]. One warp per row,
// register accumulation, single store, ZERO atomics.
// ---------------------------------------------------------------------------
__global__ void spmm_csr(int n) {
    int gt = blockIdx.x * blockDim.x + threadIdx.x;
    int row = gt >> 5, lane = gt & 31;
    if (row >= n) return;
    int beg = g_rowptr[row];
    int end = beg + g_cnt[row];
    float4 acc = make_float4(0.f, 0.f, 0.f, 0.f);
    for (int b = beg; b < end; b += 32) {
        int idx = b + lane;
        int c = 0; float w = 0.f;
        if (idx < end) { c = g_ecol[idx]; w = g_ewc[idx]; }
        int m = min(32, end - b);
        for (int j = 0; j < m; ++j) {
            int   cc = __shfl_sync(0xffffffffu, c, j);
            float ww = __shfl_sync(0xffffffffu, w, j);
            float4 v = ((const float4*)g_ego)[(size_t)cc * 32 + lane];
            acc.x += ww * v.x; acc.y += ww * v.y;
            acc.z += ww * v.z; acc.w += ww * v.w;
        }
    }
    ((float4*)g_msg)[(size_t)row * 32 + lane] = acc;
}

// ---------------------------------------------------------------------------
// Fused layer GEMM (proven R3 config: 32 nodes x 128 od, 4n x 4o, f32x2).
// ---------------------------------------------------------------------------
__global__ __launch_bounds__(256) void fused_layer(
        const float* __restrict__ gcb, const float* __restrict__ bib,
        int n, int layer) {
    __shared__ __align__(16) float As2[64 * 64];    // [kc][2*node]  16KB
    __shared__ __align__(16) float Bs[64 * 128];    // [kc][od]      32KB

    const int tid  = threadIdx.x;
    const int tn   = tid >> 5;      // warp id -> node group
    const int to   = tid & 31;      // lane    -> od group
    const int nb   = blockIdx.x * 32;
    const int loff = layer * 128;
    const float* wP = g_wPack + layer * 32768;

    unsigned long long acc[4][2];
#pragma unroll
    for (int i = 0; i < 4; ++i) { acc[i][0] = 0ull; acc[i][1] = 0ull; }

    for (int c = 0; c < 4; ++c) {
        __syncthreads();
        {
            const float4* src = (const float4*)(wP + c * 64 * 128);
            float4* dst = (float4*)Bs;
#pragma unroll
            for (int i = 0; i < 8; ++i) dst[tid + 256 * i] = src[tid + 256 * i];
        }
        {
#pragma unroll
            for (int i = 0; i < 2; ++i) {
                int idx  = tid + 256 * i;      // 0..511
                int node = idx & 31;
                int k4   = idx >> 5;           // 0..15
                int g    = nb + node;
                float4 m = make_float4(0.f, 0.f, 0.f, 0.f);
                int kk = c * 64 + k4 * 4;
                if (g < n) {
                    if (kk < 128) {
                        m = *(const float4*)(g_msg + (size_t)g * 128 + kk);
                    } else {
                        m = *(const float4*)(g_msg + (size_t)g * 128 + kk - 128);
                        float4 e = *(const float4*)(g_ego + (size_t)g * 128 + kk - 128);
                        m.x *= e.x; m.y *= e.y; m.z *= e.z; m.w *= e.w;
                    }
                }
                float* base = As2 + (k4 * 4) * 64 + 2 * node;
                *(float2*)(base)       = make_float2(m.x, m.x);
                *(float2*)(base + 64)  = make_float2(m.y, m.y);
                *(float2*)(base + 128) = make_float2(m.z, m.z);
                *(float2*)(base + 192) = make_float2(m.w, m.w);
            }
        }
        __syncthreads();
        const ulonglong2* Bu = (const ulonglong2*)Bs;
        const ulonglong2* Au = (const ulonglong2*)As2;
#pragma unroll 8
        for (int k = 0; k < 64; ++k) {
            ulonglong2 b   = Bu[k * 32 + to];
            ulonglong2 a01 = Au[k * 16 + 2 * tn];
            ulonglong2 a23 = Au[k * 16 + 2 * tn + 1];
            fma2(acc[0][0], a01.x, b.x); fma2(acc[0][1], a01.x, b.y);
            fma2(acc[1][0], a01.y, b.x); fma2(acc[1][1], a01.y, b.y);
            fma2(acc[2][0], a23.x, b.x); fma2(acc[2][1], a23.x, b.y);
            fma2(acc[3][0], a23.y, b.x); fma2(acc[3][1], a23.y, b.y);
        }
    }

    float4 bias;
    {
        float4 bg = *(const float4*)(gcb + loff + 4 * to);
        float4 bb = *(const float4*)(bib + loff + 4 * to);
        bias = make_float4(bg.x + bb.x, bg.y + bb.y, bg.z + bb.z, bg.w + bb.w);
    }

    float4 v[4];
    float  s[4];
#pragma unroll
    for (int nn = 0; nn < 4; ++nn) {
        float x0 = lo32(acc[nn][0]) + bias.x;
        float x1 = hi32(acc[nn][0]) + bias.y;
        float x2 = lo32(acc[nn][1]) + bias.z;
        float x3 = hi32(acc[nn][1]) + bias.w;
        x0 = (x0 > 0.f) ? x0 : 0.2f * x0;
        x1 = (x1 > 0.f) ? x1 : 0.2f * x1;
        x2 = (x2 > 0.f) ? x2 : 0.2f * x2;
        x3 = (x3 > 0.f) ? x3 : 0.2f * x3;
        v[nn] = make_float4(x0, x1, x2, x3);
        s[nn] = x0 * x0 + x1 * x1 + x2 * x2 + x3 * x3;
    }
#pragma unroll
    for (int off = 16; off; off >>= 1) {
        s[0] += __shfl_xor_sync(0xffffffffu, s[0], off);
        s[1] += __shfl_xor_sync(0xffffffffu, s[1], off);
        s[2] += __shfl_xor_sync(0xffffffffu, s[2], off);
        s[3] += __shfl_xor_sync(0xffffffffu, s[3], off);
    }
#pragma unroll
    for (int nn = 0; nn < 4; ++nn) {
        int g = nb + 4 * tn + nn;
        if (g < n) {
            float inv = 1.0f / fmaxf(sqrtf(s[nn]), 1e-12f);
            float4 w = v[nn];
            *(float4*)(g_ego + (size_t)g * 128 + 4 * to) = w;
            *(float4*)(g_all + (size_t)g * 512 + loff + 128 + 4 * to) =
                make_float4(w.x * inv, w.y * inv, w.z * inv, w.w * inv);
        }
    }
}

// ---------------------------------------------------------------------------
// Scoring: out[q] = dot(all[src[q]], all[dst[q]]) over 512 dims. Warp/query.
// ---------------------------------------------------------------------------
__global__ void score(const int* __restrict__ eli, int Q,
                      float* __restrict__ out) {
    int gt = blockIdx.x * blockDim.x + threadIdx.x;
    int q = gt >> 5, lane = gt & 31;
    if (q >= Q) return;
    int s = eli[q];
    int d = eli[Q + q];
    const float4* a = (const float4*)(g_all + (size_t)s * 512);
    const float4* b = (const float4*)(g_all + (size_t)d * 512);
    float acc = 0.f;
#pragma unroll
    for (int j = 0; j < 4; ++j) {
        float4 x = a[lane + 32 * j];
        float4 y = b[lane + 32 * j];
        acc += x.x * y.x + x.y * y.y + x.z * y.z + x.w * y.w;
    }
#pragma unroll
    for (int off = 16; off; off >>= 1)
        acc += __shfl_xor_sync(0xffffffffu, acc, off);
    if (lane == 0) out[q] = acc;
}

// ---------------------------------------------------------------------------
extern "C" void kernel_launch(void* const* d_in, const int* in_sizes, int n_in,
                              void* d_out, int out_size) {
    const int*   ei  = (const int*)d_in[0];    // edge_index        [2, E]
    const int*   eli = (const int*)d_in[1];    // edge_label_index  [2, Q]
    const float* ew  = (const float*)d_in[2];  // edge_weight       [E]
    const float* emb = (const float*)d_in[3];  // emb               [N, 128]
    const float* gcw = (const float*)d_in[4];  // gc_w              [3,128,128]
    const float* gcb = (const float*)d_in[5];  // gc_b              [3,128]
    const float* biw = (const float*)d_in[6];  // bi_w              [3,128,128]
    const float* bib = (const float*)d_in[7];  // bi_b              [3,128]

    int E = in_sizes[0] / 2;
    int Q = in_sizes[1] / 2;
    int n = in_sizes[3] / 128;
    float* out = (float*)d_out;

    pack_weights<<<(NLYR * 256 * 128 + 255) / 256, 256>>>(gcw, biw);
    init_copy<<<(n * 32 + 255) / 256, 256>>>((const float4*)emb, n);

    // Build CSR once; reused by all 3 layers.
    csr_hist<<<(E + 255) / 256, 256>>>(ei, E);
    csr_offsets<<<(n + 255) / 256, 256>>>(n);
    csr_scatter<<<(E + 255) / 256, 256>>>(ei, ew, E);

    for (int l = 0; l < NLYR; ++l) {
        spmm_csr<<<(int)(((size_t)n * 32 + 255) / 256), 256>>>(n);
        fused_layer<<<(n + 31) / 32, 256>>>(gcb, bib, n, l);
    }

    score<<<(int)(((size_t)Q * 32 + 255) / 256), 256>>>(eli, Q, out);
}

// round 7
// speedup vs baseline: 1.7495x; 1.1777x over previous
#include <cuda_runtime.h>

#define NMAX 100000
#define EMAX 1600000
#define NLYR 3

// Device scratch.
__device__ __align__(16) float g_all[(size_t)NMAX * 512];
__device__ __align__(16) float g_ego[(size_t)NMAX * 128];
__device__ __align__(16) float g_msg[(size_t)NMAX * 128];
__device__ __align__(16) float g_wPack[NLYR * 256 * 128];
// CSR built once per launch, reused by all 3 layers.
__device__ int   g_rowptr[NMAX];
__device__ int   g_cnt[NMAX];
__device__ int   g_off[NMAX];
__device__ int   g_total;
__device__ int   g_ecol[EMAX];
__device__ float g_ewc[EMAX];

// packed f32x2 fma: d = a*b + d
__device__ __forceinline__ void fma2(unsigned long long& d,
                                     unsigned long long a,
                                     unsigned long long b) {
    asm("fma.rn.f32x2 %0, %1, %2, %0;" : "+l"(d) : "l"(a), "l"(b));
}
__device__ __forceinline__ unsigned long long pack2(float a) {
    unsigned long long r;
    asm("mov.b64 %0, {%1, %1};" : "=l"(r) : "f"(a));
    return r;
}
__device__ __forceinline__ float lo32(unsigned long long x) {
    return __uint_as_float((unsigned)(x & 0xffffffffu));
}
__device__ __forceinline__ float hi32(unsigned long long x) {
    return __uint_as_float((unsigned)(x >> 32));
}

// ---------------------------------------------------------------------------
__global__ void pack_weights(const float* __restrict__ gw,
                             const float* __restrict__ bw) {
    int idx = blockIdx.x * blockDim.x + threadIdx.x;
    if (idx >= NLYR * 256 * 128) return;
    int l  = idx >> 15;
    int r  = idx & 32767;
    int k  = r >> 7;
    int od = r & 127;
    float v = (k < 128) ? gw[l * 16384 + od * 128 + k]
                        : bw[l * 16384 + od * 128 + (k - 128)];
    g_wPack[idx] = v;
}

// ---------------------------------------------------------------------------
__global__ void init_copy(const float4* __restrict__ emb4, int n) {
    int i = blockIdx.x * blockDim.x + threadIdx.x;
    if (i >= n * 32) return;
    int node = i >> 5, d4 = i & 31;
    float4 v = emb4[i];
    ((float4*)g_all)[(size_t)node * 128 + d4] = v;
    ((float4*)g_ego)[i] = v;
    if (d4 == 0) { g_cnt[node] = 0; g_off[node] = 0; }
    if (i == 0) g_total = 0;
}

// ---------------------------------------------------------------------------
// CSR build: histogram -> hierarchical offset reservation -> scatter.
// ---------------------------------------------------------------------------
__global__ void csr_hist(const int* __restrict__ ei, int E) {
    int e = blockIdx.x * blockDim.x + threadIdx.x;
    if (e < E) atomicAdd(&g_cnt[ei[e]], 1);
}

__global__ __launch_bounds__(256) void csr_offsets(int n) {
    __shared__ int wbase[8];
    int tid  = threadIdx.x;
    int lane = tid & 31;
    int w    = tid >> 5;
    int i    = blockIdx.x * 256 + tid;
    int cnt  = (i < n) ? g_cnt[i] : 0;

    int pre = cnt;
#pragma unroll
    for (int off = 1; off < 32; off <<= 1) {
        int v = __shfl_up_sync(0xffffffffu, pre, off);
        if (lane >= off) pre += v;
    }
    if (lane == 31) wbase[w] = pre;
    __syncthreads();

    if (w == 0) {
        int orig = (lane < 8) ? wbase[lane] : 0;
        int s = orig;
#pragma unroll
        for (int off = 1; off < 8; off <<= 1) {
            int v = __shfl_up_sync(0xffffffffu, s, off);
            if (lane >= off) s += v;
        }
        int total = __shfl_sync(0xffffffffu, s, 7);
        int base = 0;
        if (lane == 7) base = atomicAdd(&g_total, total);
        base = __shfl_sync(0xffffffffu, base, 7);
        if (lane < 8) wbase[lane] = base + s - orig;
    }
    __syncthreads();

    if (i < n) g_rowptr[i] = wbase[w] + pre - cnt;
}

__global__ void csr_scatter(const int* __restrict__ ei,
                            const float* __restrict__ ew, int E) {
    int e = blockIdx.x * blockDim.x + threadIdx.x;
    if (e >= E) return;
    int row = ei[e];
    int col = ei[E + e];
    int pos = g_rowptr[row] + atomicAdd(&g_off[row], 1);
    g_ecol[pos] = col;
    g_ewc[pos]  = ew[e];
}

// ---------------------------------------------------------------------------
// SpMM via CSR: one warp per row, register accumulation, zero atomics.
// ---------------------------------------------------------------------------
__global__ void spmm_csr(int n) {
    int gt = blockIdx.x * blockDim.x + threadIdx.x;
    int row = gt >> 5, lane = gt & 31;
    if (row >= n) return;
    int beg = g_rowptr[row];
    int end = beg + g_cnt[row];
    float4 acc = make_float4(0.f, 0.f, 0.f, 0.f);
    for (int b = beg; b < end; b += 32) {
        int idx = b + lane;
        int c = 0; float w = 0.f;
        if (idx < end) { c = g_ecol[idx]; w = g_ewc[idx]; }
        int m = min(32, end - b);
        for (int j = 0; j < m; ++j) {
            int   cc = __shfl_sync(0xffffffffu, c, j);
            float ww = __shfl_sync(0xffffffffu, w, j);
            float4 v = ((const float4*)g_ego)[(size_t)cc * 32 + lane];
            acc.x += ww * v.x; acc.y += ww * v.y;
            acc.z += ww * v.z; acc.w += ww * v.w;
        }
    }
    ((float4*)g_msg)[(size_t)row * 32 + lane] = acc;
}

// ---------------------------------------------------------------------------
// Fused layer GEMM, broadcast-B / lane-distinct-A mapping, f32x2.
//   Tile: 64 nodes x 128 ods per block (512 thr, 16 warps).
//   Warp w -> ods [8w, 8w+8); lane l -> nodes {l, l+32}.
//   Per k per thread: 2 LDS.32 (A, 128B distinct/warp) + 2 LDS.128 (B,
//   broadcast) + 2 pack + 8 FFMA2  -> 4 smem wavefronts per 8 FFMA2.
// ---------------------------------------------------------------------------
__global__ __launch_bounds__(512) void fused_layer(
        const float* __restrict__ gcb, const float* __restrict__ bib,
        int n, int layer) {
    __shared__ __align__(16) float As[32 * 65];    // [kc][node], pad 65
    __shared__ __align__(16) float Bs[32 * 128];   // [kc][od]
    __shared__ float invS[64];

    const int tid  = threadIdx.x;
    const int lane = tid & 31;
    const int w    = tid >> 5;         // 0..15
    const int odb  = w * 8;
    const int nb   = blockIdx.x * 64;
    const int loff = layer * 128;
    const float* wP = g_wPack + layer * 32768;

    // A-fill task for this thread (constant across chunks)
    const int fk4   = tid & 7;         // 0..7  -> k quad within chunk
    const int fnode = tid >> 3;        // 0..63
    const int fg    = nb + fnode;

    unsigned long long acc[2][4];
#pragma unroll
    for (int i = 0; i < 2; ++i)
#pragma unroll
        for (int j = 0; j < 4; ++j) acc[i][j] = 0ull;

    for (int c = 0; c < 8; ++c) {
        __syncthreads();
        // --- B fill: 1024 float4 over 512 threads, coalesced
        {
            const float4* src = (const float4*)(wP + c * 32 * 128);
            float4* dst = (float4*)Bs;
            dst[tid]       = src[tid];
            dst[tid + 512] = src[tid + 512];
        }
        // --- A fill: one float4 of A per thread, transposed into As[k][node]
        {
            int kk = c * 32 + fk4 * 4;
            float4 m = make_float4(0.f, 0.f, 0.f, 0.f);
            if (fg < n) {
                if (kk < 128) {
                    m = *(const float4*)(g_msg + (size_t)fg * 128 + kk);
                } else {
                    m = *(const float4*)(g_msg + (size_t)fg * 128 + kk - 128);
                    float4 e = *(const float4*)(g_ego + (size_t)fg * 128 + kk - 128);
                    m.x *= e.x; m.y *= e.y; m.z *= e.z; m.w *= e.w;
                }
            }
            float* base = As + (fk4 * 4) * 65 + fnode;
            base[0]   = m.x;
            base[65]  = m.y;
            base[130] = m.z;
            base[195] = m.w;
        }
        __syncthreads();
        // --- compute 32 k-steps
#pragma unroll 8
        for (int k = 0; k < 32; ++k) {
            float a0 = As[k * 65 + lane];
            float a1 = As[k * 65 + 32 + lane];
            const ulonglong2* Bu = (const ulonglong2*)(Bs + k * 128 + odb);
            ulonglong2 b0 = Bu[0];     // ods odb..odb+3 (broadcast)
            ulonglong2 b1 = Bu[1];     // ods odb+4..odb+7
            unsigned long long p0 = pack2(a0);
            unsigned long long p1 = pack2(a1);
            fma2(acc[0][0], p0, b0.x); fma2(acc[0][1], p0, b0.y);
            fma2(acc[0][2], p0, b1.x); fma2(acc[0][3], p0, b1.y);
            fma2(acc[1][0], p1, b0.x); fma2(acc[1][1], p1, b0.y);
            fma2(acc[1][2], p1, b1.x); fma2(acc[1][3], p1, b1.y);
        }
    }

    // --- epilogue ---
    float bias[8];
    {
        float4 bg0 = *(const float4*)(gcb + loff + odb);
        float4 bg1 = *(const float4*)(gcb + loff + odb + 4);
        float4 bb0 = *(const float4*)(bib + loff + odb);
        float4 bb1 = *(const float4*)(bib + loff + odb + 4);
        bias[0] = bg0.x + bb0.x; bias[1] = bg0.y + bb0.y;
        bias[2] = bg0.z + bb0.z; bias[3] = bg0.w + bb0.w;
        bias[4] = bg1.x + bb1.x; bias[5] = bg1.y + bb1.y;
        bias[6] = bg1.z + bb1.z; bias[7] = bg1.w + bb1.w;
    }

    float v[2][8];
    float s[2];
#pragma unroll
    for (int nn = 0; nn < 2; ++nn) {
        float sum = 0.f;
#pragma unroll
        for (int j = 0; j < 4; ++j) {
            float x0 = lo32(acc[nn][j]) + bias[2 * j];
            float x1 = hi32(acc[nn][j]) + bias[2 * j + 1];
            x0 = (x0 > 0.f) ? x0 : 0.2f * x0;
            x1 = (x1 > 0.f) ? x1 : 0.2f * x1;
            v[nn][2 * j]     = x0;
            v[nn][2 * j + 1] = x1;
            sum += x0 * x0 + x1 * x1;
        }
        s[nn] = sum;
    }

    // cross-warp L2-norm reduction: reuse As as red[16][64]
    __syncthreads();
    As[w * 64 + lane]      = s[0];
    As[w * 64 + 32 + lane] = s[1];
    __syncthreads();
    if (tid < 64) {
        float t = 0.f;
#pragma unroll
        for (int ww = 0; ww < 16; ++ww) t += As[ww * 64 + tid];
        invS[tid] = 1.0f / fmaxf(sqrtf(t), 1e-12f);
    }
    __syncthreads();

#pragma unroll
    for (int nn = 0; nn < 2; ++nn) {
        int node = lane + 32 * nn;
        int g = nb + node;
        if (g < n) {
            float inv = invS[node];
            float4 w0 = make_float4(v[nn][0], v[nn][1], v[nn][2], v[nn][3]);
            float4 w1 = make_float4(v[nn][4], v[nn][5], v[nn][6], v[nn][7]);
            *(float4*)(g_ego + (size_t)g * 128 + odb)     = w0;
            *(float4*)(g_ego + (size_t)g * 128 + odb + 4) = w1;
            *(float4*)(g_all + (size_t)g * 512 + loff + 128 + odb) =
                make_float4(w0.x * inv, w0.y * inv, w0.z * inv, w0.w * inv);
            *(float4*)(g_all + (size_t)g * 512 + loff + 128 + odb + 4) =
                make_float4(w1.x * inv, w1.y * inv, w1.z * inv, w1.w * inv);
        }
    }
}

// ---------------------------------------------------------------------------
// Scoring: out[q] = dot(all[src[q]], all[dst[q]]) over 512 dims. Warp/query.
// ---------------------------------------------------------------------------
__global__ void score(const int* __restrict__ eli, int Q,
                      float* __restrict__ out) {
    int gt = blockIdx.x * blockDim.x + threadIdx.x;
    int q = gt >> 5, lane = gt & 31;
    if (q >= Q) return;
    int s = eli[q];
    int d = eli[Q + q];
    const float4* a = (const float4*)(g_all + (size_t)s * 512);
    const float4* b = (const float4*)(g_all + (size_t)d * 512);
    float acc = 0.f;
#pragma unroll
    for (int j = 0; j < 4; ++j) {
        float4 x = a[lane + 32 * j];
        float4 y = b[lane + 32 * j];
        acc += x.x * y.x + x.y * y.y + x.z * y.z + x.w * y.w;
    }
#pragma unroll
    for (int off = 16; off; off >>= 1)
        acc += __shfl_xor_sync(0xffffffffu, acc, off);
    if (lane == 0) out[q] = acc;
}

// ---------------------------------------------------------------------------
extern "C" void kernel_launch(void* const* d_in, const int* in_sizes, int n_in,
                              void* d_out, int out_size) {
    const int*   ei  = (const int*)d_in[0];
    const int*   eli = (const int*)d_in[1];
    const float* ew  = (const float*)d_in[2];
    const float* emb = (const float*)d_in[3];
    const float* gcw = (const float*)d_in[4];
    const float* gcb = (const float*)d_in[5];
    const float* biw = (const float*)d_in[6];
    const float* bib = (const float*)d_in[7];

    int E = in_sizes[0] / 2;
    int Q = in_sizes[1] / 2;
    int n = in_sizes[3] / 128;
    float* out = (float*)d_out;

    pack_weights<<<(NLYR * 256 * 128 + 255) / 256, 256>>>(gcw, biw);
    init_copy<<<(n * 32 + 255) / 256, 256>>>((const float4*)emb, n);

    csr_hist<<<(E + 255) / 256, 256>>>(ei, E);
    csr_offsets<<<(n + 255) / 256, 256>>>(n);
    csr_scatter<<<(E + 255) / 256, 256>>>(ei, ew, E);

    for (int l = 0; l < NLYR; ++l) {
        spmm_csr<<<(int)(((size_t)n * 32 + 255) / 256), 256>>>(n);
        fused_layer<<<(n + 63) / 64, 512>>>(gcb, bib, n, l);
    }

    score<<<(int)(((size_t)Q * 32 + 255) / 256), 256>>>(eli, Q, out);
}